// round 4
// baseline (speedup 1.0000x reference)
#include <cuda_runtime.h>

#define N_NODES 100000
#define E_TOTAL 1000000
#define IN_DIM  128

// Per-node precomputed projections: row layout [A(128) | B(128)]
// A = z @ W1[0:128, :], B = z @ W1[128:256, :]
__device__ float g_AB[(size_t)N_NODES * 256];

// ---------------------------------------------------------------------------
// Kernel 1: GEMM  out[m][jb*128+j] = sum_k z[m][k] * W1[(jb*128+k)*128 + j]
// M=100000, N=256 (two 128-col blocks), K=128.
// BM=64, BN=128, BK=32, 256 threads, 4x8 microtile per thread.
// ---------------------------------------------------------------------------
__global__ __launch_bounds__(256) void precompute_kernel(
    const float* __restrict__ z,
    const float* __restrict__ W1)
{
    __shared__ float As[32][68];    // transposed: As[k][m], stride 68 keeps float4 16B-aligned
    __shared__ float Bs[32][128];

    const int tid  = threadIdx.x;
    const int bm   = blockIdx.x;    // 0..1562  (64 rows each)
    const int jb   = blockIdx.y;    // 0..1     (which 128-col half of W1-cat)
    const int trow = tid >> 4;      // 0..15 -> rows trow*4 .. +3
    const int tcol = tid & 15;      // 0..15 -> cols {tcol*4..+3} and {64+tcol*4..+3}

    float acc[4][8];
#pragma unroll
    for (int r = 0; r < 4; r++)
#pragma unroll
        for (int c = 0; c < 8; c++) acc[r][c] = 0.f;

    for (int k0 = 0; k0 < 128; k0 += 32) {
        // --- load A tile (64 rows x 32 k), transposed into As[k][m] ---
#pragma unroll
        for (int i = 0; i < 2; i++) {
            int flat4 = tid + 256 * i;       // 0..511
            int m     = flat4 >> 3;          // 0..63
            int kk4   = flat4 & 7;           // 0..7  (float4 index along k)
            int gm    = bm * 64 + m;
            float4 v  = make_float4(0.f, 0.f, 0.f, 0.f);
            if (gm < N_NODES)
                v = *(const float4*)(z + (size_t)gm * IN_DIM + k0 + kk4 * 4);
            As[kk4 * 4 + 0][m] = v.x;
            As[kk4 * 4 + 1][m] = v.y;
            As[kk4 * 4 + 2][m] = v.z;
            As[kk4 * 4 + 3][m] = v.w;
        }
        // --- load B tile (32 k x 128 cols) from W1 ---
#pragma unroll
        for (int i = 0; i < 4; i++) {
            int flat4 = tid + 256 * i;       // 0..1023
            int kk    = flat4 >> 5;          // 0..31
            int j4    = flat4 & 31;          // 0..31
            float4 w  = *(const float4*)(W1 + (size_t)(jb * 128 + k0 + kk) * 128 + j4 * 4);
            *(float4*)&Bs[kk][j4 * 4] = w;
        }
        __syncthreads();

#pragma unroll
        for (int kk = 0; kk < 32; kk++) {
            float4 a   = *(const float4*)&As[kk][trow * 4];
            float4 b0  = *(const float4*)&Bs[kk][tcol * 4];
            float4 b1v = *(const float4*)&Bs[kk][64 + tcol * 4];
            float av[4] = {a.x, a.y, a.z, a.w};
            float bv[8] = {b0.x, b0.y, b0.z, b0.w, b1v.x, b1v.y, b1v.z, b1v.w};
#pragma unroll
            for (int r = 0; r < 4; r++)
#pragma unroll
                for (int c = 0; c < 8; c++)
                    acc[r][c] = fmaf(av[r], bv[c], acc[r][c]);
        }
        __syncthreads();
    }

    // --- store ---
#pragma unroll
    for (int r = 0; r < 4; r++) {
        int gm = bm * 64 + trow * 4 + r;
        if (gm < N_NODES) {
            float* dst = g_AB + (size_t)gm * 256 + jb * 128;
            float4 v0 = make_float4(acc[r][0], acc[r][1], acc[r][2], acc[r][3]);
            float4 v1 = make_float4(acc[r][4], acc[r][5], acc[r][6], acc[r][7]);
            *(float4*)(dst + tcol * 4)      = v0;
            *(float4*)(dst + 64 + tcol * 4) = v1;
        }
    }
}

// ---------------------------------------------------------------------------
// Kernel 2: per-edge. One warp per edge.
// logit = sum_j relu(A[src][j] + B[dst][j] + b1[j]) * W2[j];  out = sigmoid(logit+b2)
// edge_index is int32 on device (JAX default x64-disabled downcasts int64).
// ---------------------------------------------------------------------------
__global__ __launch_bounds__(256) void edge_kernel(
    const int* __restrict__ ei,         // [2, E] int32
    const float* __restrict__ b1,       // [128]
    const float* __restrict__ W2,       // [128]
    const float* __restrict__ b2,       // [1]
    float* __restrict__ out)            // [E]
{
    int gwarp = (blockIdx.x * blockDim.x + threadIdx.x) >> 5;
    int lane  = threadIdx.x & 31;
    if (gwarp >= E_TOTAL) return;

    int src = ei[gwarp];
    int dst = ei[E_TOTAL + gwarp];

    const float4 a  = *(const float4*)(g_AB + (size_t)src * 256 + lane * 4);
    const float4 b  = *(const float4*)(g_AB + (size_t)dst * 256 + 128 + lane * 4);
    const float4 bb = *(const float4*)(b1 + lane * 4);
    const float4 w  = *(const float4*)(W2 + lane * 4);

    float h0 = fmaxf(a.x + b.x + bb.x, 0.f);
    float h1 = fmaxf(a.y + b.y + bb.y, 0.f);
    float h2 = fmaxf(a.z + b.z + bb.z, 0.f);
    float h3 = fmaxf(a.w + b.w + bb.w, 0.f);

    float p = h0 * w.x + h1 * w.y + h2 * w.z + h3 * w.w;
#pragma unroll
    for (int off = 16; off > 0; off >>= 1)
        p += __shfl_xor_sync(0xffffffff, p, off);

    if (lane == 0) {
        float logit = p + b2[0];
        out[gwarp] = 1.f / (1.f + __expf(-logit));
    }
}

// ---------------------------------------------------------------------------
extern "C" void kernel_launch(void* const* d_in, const int* in_sizes, int n_in,
                              void* d_out, int out_size)
{
    const float* z   = (const float*)d_in[0];
    const int*   ei  = (const int*)d_in[1];     // int32 edge_index
    const float* W1  = (const float*)d_in[2];
    const float* b1  = (const float*)d_in[3];
    const float* W2  = (const float*)d_in[4];
    const float* b2  = (const float*)d_in[5];
    float*       out = (float*)d_out;

    dim3 grid_pre((N_NODES + 63) / 64, 2);
    precompute_kernel<<<grid_pre, 256>>>(z, W1);

    int warps_total = E_TOTAL;                         // 1 warp per edge
    int blocks = (warps_total * 32 + 255) / 256;       // 8 edges per block
    edge_kernel<<<blocks, 256>>>(ei, b1, W2, b2, out);
}

// round 13
// speedup vs baseline: 2.0156x; 2.0156x over previous
#include <cuda_runtime.h>
#include <cuda_fp16.h>
#include <mma.h>

using namespace nvcuda;

#define N_NODES 100000
#define E_TOTAL 1000000
#define IN_DIM  128
#define EPW     4          // edges per warp

// Per-node precomputed projections, fp16: row layout [A+b1 (128) | B (128)]
// A = z @ W1[0:128, :] + b1,  B = z @ W1[128:256, :]
__device__ __half g_AB[(size_t)N_NODES * 256];

// Shared layout (dynamic):
//   As: 64 x 136 fp16   (17408 B)   z tile,  ld=136
//   Bs: 128 x 136 fp16  (34816 B)   W1 half, ld=136
//   Cs: 8 x (16x64) f32 (32768 B)   per-warp accum staging, ld=64
#define AS_LD   136
#define BS_LD   136
#define AS_BYTES 17408
#define BS_BYTES 34816
#define SMEM_TOTAL (AS_BYTES + BS_BYTES + 32768)

// ---------------------------------------------------------------------------
// Kernel 1: fp16 HMMA GEMM.  For each 64-row block of z, compute both 128-col
// halves of [z@W1_top + b1 | z@W1_bot], fp32 accum, fp16 store to g_AB.
// 256 threads = 8 warps laid out 4(M) x 2(N); each warp does 16x64.
// ---------------------------------------------------------------------------
__global__ __launch_bounds__(256) void precompute_kernel(
    const float* __restrict__ z,
    const float* __restrict__ W1,
    const float* __restrict__ b1)
{
    extern __shared__ __align__(32) char smem[];
    __half* As = (__half*)smem;
    __half* Bs = (__half*)(smem + AS_BYTES);
    float*  Cs = (float*)(smem + AS_BYTES + BS_BYTES);

    const int tid  = threadIdx.x;
    const int bm   = blockIdx.x;          // 64 rows each
    const int wid  = tid >> 5;
    const int lane = tid & 31;
    const int wm   = wid & 3;             // M sub-tile (16 rows)
    const int wn   = wid >> 2;            // N strip (64 cols)

    // --- load As: 64 x 128 fp32 -> fp16, zero-pad invalid rows ---
#pragma unroll
    for (int i = 0; i < 8; i++) {
        int flat4 = tid + 256 * i;        // 0..2047
        int m     = flat4 >> 5;           // 0..63
        int k4    = flat4 & 31;           // 0..31
        int gm    = bm * 64 + m;
        float4 v  = make_float4(0.f, 0.f, 0.f, 0.f);
        if (gm < N_NODES)
            v = *(const float4*)(z + (size_t)gm * IN_DIM + k4 * 4);
        __half2 h[2];
        h[0] = __floats2half2_rn(v.x, v.y);
        h[1] = __floats2half2_rn(v.z, v.w);
        *(uint2*)(As + m * AS_LD + k4 * 4) = *(uint2*)h;
    }

    for (int jb = 0; jb < 2; jb++) {
        __syncthreads();   // As ready (jb=0) / all warps done with prev Bs

        // --- load Bs: W1[jb*128 .. +128) x 128 fp32 -> fp16 ---
#pragma unroll
        for (int i = 0; i < 16; i++) {
            int flat4 = tid + 256 * i;    // 0..4095
            int kk    = flat4 >> 5;       // 0..127
            int j4    = flat4 & 31;       // 0..31
            float4 v  = *(const float4*)(W1 + (size_t)(jb * 128 + kk) * 128 + j4 * 4);
            __half2 h[2];
            h[0] = __floats2half2_rn(v.x, v.y);
            h[1] = __floats2half2_rn(v.z, v.w);
            *(uint2*)(Bs + kk * BS_LD + j4 * 4) = *(uint2*)h;
        }
        __syncthreads();

        // --- MMA: warp computes rows wm*16..+15, cols wn*64..+63 ---
        wmma::fragment<wmma::accumulator, 16, 16, 16, float> cf[4];
#pragma unroll
        for (int nn = 0; nn < 4; nn++) wmma::fill_fragment(cf[nn], 0.f);

#pragma unroll
        for (int k = 0; k < 8; k++) {
            wmma::fragment<wmma::matrix_a, 16, 16, 16, __half, wmma::row_major> af;
            wmma::load_matrix_sync(af, As + (wm * 16) * AS_LD + k * 16, AS_LD);
#pragma unroll
            for (int nn = 0; nn < 4; nn++) {
                wmma::fragment<wmma::matrix_b, 16, 16, 16, __half, wmma::row_major> bf;
                wmma::load_matrix_sync(bf, Bs + (k * 16) * BS_LD + wn * 64 + nn * 16, BS_LD);
                wmma::mma_sync(cf[nn], af, bf, cf[nn]);
            }
        }

        // --- epilogue: stage to Cs (per-warp 16x64, ld=64), fold bias, fp16 store ---
        float* cwarp = Cs + wid * 16 * 64;
#pragma unroll
        for (int nn = 0; nn < 4; nn++)
            wmma::store_matrix_sync(cwarp + nn * 16, cf[nn], 64, wmma::mem_row_major);
        __syncwarp();

        {
            int r  = lane >> 1;           // 0..15
            int c0 = (lane & 1) * 32;     // 0 or 32
            int gm = bm * 64 + wm * 16 + r;
            if (gm < N_NODES) {
                __half* dst = g_AB + (size_t)gm * 256 + jb * 128 + wn * 64 + c0;
                const float* srow = cwarp + r * 64 + c0;
#pragma unroll
                for (int cc = 0; cc < 8; cc++) {
                    int jcol = wn * 64 + c0 + cc * 4;
                    float f0 = srow[cc * 4 + 0];
                    float f1 = srow[cc * 4 + 1];
                    float f2 = srow[cc * 4 + 2];
                    float f3 = srow[cc * 4 + 3];
                    if (jb == 0) {
                        f0 += __ldg(b1 + jcol + 0);
                        f1 += __ldg(b1 + jcol + 1);
                        f2 += __ldg(b1 + jcol + 2);
                        f3 += __ldg(b1 + jcol + 3);
                    }
                    __half2 h[2];
                    h[0] = __floats2half2_rn(f0, f1);
                    h[1] = __floats2half2_rn(f2, f3);
                    *(uint2*)(dst + cc * 4) = *(uint2*)h;
                }
            }
        }
    }
}

// ---------------------------------------------------------------------------
// Kernel 2: per-edge. One warp handles EPW edges; all gathers issued first.
// logit = sum_j relu(A'[src][j] + B[dst][j]) * W2[j];  out = sigmoid(logit+b2)
// ---------------------------------------------------------------------------
__global__ __launch_bounds__(256) void edge_kernel(
    const int* __restrict__ ei,         // [2, E] int32
    const float* __restrict__ W2,       // [128]
    const float* __restrict__ b2,       // [1]
    float* __restrict__ out)            // [E]
{
    int warp = (blockIdx.x * blockDim.x + threadIdx.x) >> 5;
    int lane = threadIdx.x & 31;
    int base = warp * EPW;
    if (base >= E_TOTAL) return;

    const float4 w = *(const float4*)(W2 + lane * 4);
    const float b2v = __ldg(b2);

    int srcs[EPW], dsts[EPW];
#pragma unroll
    for (int e = 0; e < EPW; e++) {
        srcs[e] = ei[base + e];
        dsts[e] = ei[E_TOTAL + base + e];
    }

    // issue all gathers back-to-back (8 outstanding LDG.64)
    uint2 ra[EPW], rb[EPW];
    const __half* gh = g_AB;
#pragma unroll
    for (int e = 0; e < EPW; e++) {
        ra[e] = *(const uint2*)(gh + (size_t)srcs[e] * 256 + lane * 4);
        rb[e] = *(const uint2*)(gh + (size_t)dsts[e] * 256 + 128 + lane * 4);
    }

#pragma unroll
    for (int e = 0; e < EPW; e++) {
        __half2 a01 = *(__half2*)&ra[e].x;
        __half2 a23 = *(__half2*)&ra[e].y;
        __half2 b01 = *(__half2*)&rb[e].x;
        __half2 b23 = *(__half2*)&rb[e].y;
        float2 fa01 = __half22float2(a01);
        float2 fa23 = __half22float2(a23);
        float2 fb01 = __half22float2(b01);
        float2 fb23 = __half22float2(b23);

        float h0 = fmaxf(fa01.x + fb01.x, 0.f);
        float h1 = fmaxf(fa01.y + fb01.y, 0.f);
        float h2 = fmaxf(fa23.x + fb23.x, 0.f);
        float h3 = fmaxf(fa23.y + fb23.y, 0.f);

        float p = h0 * w.x + h1 * w.y + h2 * w.z + h3 * w.w;
#pragma unroll
        for (int off = 16; off > 0; off >>= 1)
            p += __shfl_xor_sync(0xffffffff, p, off);

        if (lane == 0) {
            float logit = p + b2v;
            out[base + e] = 1.f / (1.f + __expf(-logit));
        }
    }
}

// ---------------------------------------------------------------------------
extern "C" void kernel_launch(void* const* d_in, const int* in_sizes, int n_in,
                              void* d_out, int out_size)
{
    const float* z   = (const float*)d_in[0];
    const int*   ei  = (const int*)d_in[1];     // int32 edge_index
    const float* W1  = (const float*)d_in[2];
    const float* b1  = (const float*)d_in[3];
    const float* W2  = (const float*)d_in[4];
    const float* b2  = (const float*)d_in[5];
    float*       out = (float*)d_out;

    // idempotent, host-side only; no static guard (harness forbids them)
    cudaFuncSetAttribute(precompute_kernel,
                         cudaFuncAttributeMaxDynamicSharedMemorySize, SMEM_TOTAL);

    int grid_pre = (N_NODES + 63) / 64;                 // 1563 blocks
    precompute_kernel<<<grid_pre, 256, SMEM_TOTAL>>>(z, W1, b1);

    int warps_total = (E_TOTAL + EPW - 1) / EPW;        // 250000 warps
    int blocks = (warps_total * 32 + 255) / 256;        // 31250 blocks
    edge_kernel<<<blocks, 256>>>(ei, W2, b2, out);
}